// round 9
// baseline (speedup 1.0000x reference)
#include <cuda_runtime.h>
#include <mma.h>
#include <cstdint>

using namespace nvcuda;

#define B_SZ 256
#define IN_DIM 1024
#define NK 100
#define DK 50
#define NOUT 5000
#define OUT_DIM 1124

#define QROW 52                 // bytes per (k,i): 50 + 2 pad
#define QW 13                   // u32 words per (k,i)

#define SX 25.4f                // x quant scale
#define SW 4024.0f              // w quant scale (covers limit=0.03156)
#define QC (32.0f / (SX * SW))  // s32 accum -> (32 * act) combined scale

// -------------------- device scratch (no cudaMalloc allowed) ---------------
__device__ signed char   g_x8[B_SZ * IN_DIM];          // x int8 [i][k]
__device__ unsigned char g_actq8[NK * B_SZ * QROW];    // quantized act [k][i][52B]

__device__ __forceinline__ signed char q8(float v, float s) {
    int q = __float2int_rn(v * s);
    return (signed char)max(-127, min(127, q));
}

// ---------------------------------------------------------------------------
// prep: x -> int8 ; out init (copy x / zero features) ; actq pad bytes = 0x80
// ---------------------------------------------------------------------------
#define XQ_UNITS (B_SZ * IN_DIM / 4)     // 65536
#define OI_UNITS (B_SZ * OUT_DIM / 4)    // 71936
#define PAD_UNITS (NK * B_SZ)            // 25600

__global__ void prep_kernel(const float* __restrict__ x, float* __restrict__ out) {
    int t = blockIdx.x * blockDim.x + threadIdx.x;
    if (t < XQ_UNITS) {
        float4 v = ((const float4*)x)[t];
        char4 c = make_char4(q8(v.x, SX), q8(v.y, SX), q8(v.z, SX), q8(v.w, SX));
        *(char4*)&g_x8[t * 4] = c;
        return;
    }
    t -= XQ_UNITS;
    if (t < OI_UNITS) {
        int row = t / (OUT_DIM / 4);
        int c4  = t % (OUT_DIM / 4);
        float4 v = make_float4(0.f, 0.f, 0.f, 0.f);
        if (c4 < IN_DIM / 4) v = ((const float4*)x)[row * (IN_DIM / 4) + c4];
        ((float4*)out)[row * (OUT_DIM / 4) + c4] = v;
        return;
    }
    t -= OI_UNITS;
    if (t < PAD_UNITS)
        *(unsigned short*)&g_actq8[t * QROW + DK] = 0x8080;   // SAD(pad)=0
}

// ---------------------------------------------------------------------------
// int8 IMMA GEMM + fused quantization.
// act[256,5000] = (x_s8 @ w_s8) * (1/(SX*SW)), quantized to offset-u8 directly.
// Block tile 256M x 48N, GBK=64, grid (105,1) = one wave, w read ONCE.
// 12 warps = 4M x 3N, warp tile 64x16. Reg-prefetch double buffer.
// ---------------------------------------------------------------------------
#define GBN 48
#define GBK 64
#define NTILE 105              // ceil(5000/48)
#define ALD 80                 // s8 row stride A tile
#define BLD 64                 // s8 row stride B tile
#define A_ST (B_SZ * ALD)      // 20480
#define B_ST (GBK * BLD)       // 4096
#define SM_TOTAL (2 * A_ST + 2 * B_ST)   // 49152 (= 48KB static limit)

__global__ __launch_bounds__(384) void gemm_kernel(const float* __restrict__ w) {
    __shared__ __align__(16) unsigned char sm[SM_TOTAL];
    signed char* As = (signed char*)sm;                 // [2][256][80]
    signed char* Bs = (signed char*)(sm + 2 * A_ST);    // [2][64][64]
    int*         Es = (int*)sm;                         // [128][52] per half

    int tid = threadIdx.x;
    int wid = tid / 32;
    int n0 = blockIdx.x * GBN;
    int wm = (wid / 3) * 64;       // 0,64,128,192
    int wn = (wid % 3) * 16;       // 0,16,32

    uint4  apre[3];
    float4 bpre[2];

    auto ldg = [&](int kk) {
        #pragma unroll
        for (int p = 0; p < 3; p++) {
            int idx = tid + p * 384;
            if (idx < 1024) {
                int r = idx >> 2, c = (idx & 3) * 16;
                apre[p] = *(const uint4*)&g_x8[r * IN_DIM + kk + c];
            }
        }
        #pragma unroll
        for (int p = 0; p < 2; p++) {
            int idx = tid + p * 384;
            int r = idx / 12, c4 = (idx % 12) * 4;
            int n = n0 + c4;
            bpre[p] = (n < NOUT) ? *(const float4*)&w[(long long)(kk + r) * NOUT + n]
                                 : make_float4(0.f, 0.f, 0.f, 0.f);
        }
    };
    auto sts = [&](int st) {
        signed char* A = As + st * A_ST;
        signed char* B = Bs + st * B_ST;
        #pragma unroll
        for (int p = 0; p < 3; p++) {
            int idx = tid + p * 384;
            if (idx < 1024) {
                int r = idx >> 2, c = (idx & 3) * 16;
                *(uint4*)&A[r * ALD + c] = apre[p];
            }
        }
        #pragma unroll
        for (int p = 0; p < 2; p++) {
            int idx = tid + p * 384;
            int r = idx / 12, c4 = (idx % 12) * 4;
            float4 v = bpre[p];
            char4 c = make_char4(q8(v.x, SW), q8(v.y, SW), q8(v.z, SW), q8(v.w, SW));
            *(char4*)&B[r * BLD + c4] = c;
        }
    };

    wmma::fragment<wmma::matrix_a, 16, 16, 16, signed char, wmma::row_major> af;
    wmma::fragment<wmma::matrix_b, 16, 16, 16, signed char, wmma::row_major> bf;
    wmma::fragment<wmma::accumulator, 16, 16, 16, int> acc[4];
    #pragma unroll
    for (int f = 0; f < 4; f++) wmma::fill_fragment(acc[f], 0);

    ldg(0);
    sts(0);

    const int NIT = IN_DIM / GBK;    // 16
    for (int kt = 0; kt < NIT; kt++) {
        __syncthreads();
        if (kt + 1 < NIT) ldg((kt + 1) * GBK);

        const signed char* A = As + (kt & 1) * A_ST;
        const signed char* B = Bs + (kt & 1) * B_ST;
        #pragma unroll
        for (int ks = 0; ks < GBK / 16; ks++) {
            wmma::load_matrix_sync(bf, B + (ks * 16) * BLD + wn, BLD);
            #pragma unroll
            for (int f = 0; f < 4; f++) {
                wmma::load_matrix_sync(af, A + (wm + f * 16) * ALD + ks * 16, ALD);
                wmma::mma_sync(acc[f], af, bf, acc[f]);
            }
        }

        if (kt + 1 < NIT) sts((kt + 1) & 1);
    }
    __syncthreads();

    // ---- epilogue: two 128-row halves through smem, quantize to u8 ----
    int my_half = wm >> 7;               // 0 for wm 0/64, 1 for wm 128/192
    #pragma unroll
    for (int h = 0; h < 2; h++) {
        if (my_half == h) {
            #pragma unroll
            for (int f = 0; f < 4; f++)
                wmma::store_matrix_sync(&Es[((wm & 127) + f * 16) * 52 + wn],
                                        acc[f], 52, wmma::mem_row_major);
        }
        __syncthreads();
        {
            int c = tid % 48, chunk = tid / 48;    // 8 chunks x 16 rows
            int n = n0 + c;
            if (n < NOUT) {
                int k = n / DK, d = n - k * DK;
                unsigned char* dst = &g_actq8[(k * B_SZ + h * 128 + chunk * 16) * QROW + d];
                #pragma unroll
                for (int rr = 0; rr < 16; rr++) {
                    int v = Es[(chunk * 16 + rr) * 52 + c];
                    int q = __float2int_rn((float)v * QC);
                    q = max(-127, min(127, q)) + 128;
                    dst[rr * QROW] = (unsigned char)q;
                }
            }
        }
        __syncthreads();
    }
}

// ---------------------------------------------------------------------------
// features[i,k] = sum_j exp(-sum_d |act[i,k,d]-act[j,k,d]|)  via u8 SIMD SAD
// grid = (NK, 8): block = kernel k, 32-row j-chunk, 256 threads = 256 i.
// ---------------------------------------------------------------------------
#define JC 32

__device__ __forceinline__ unsigned vad4(unsigned a, unsigned b, unsigned c) {
    unsigned d;
    asm("vabsdiff4.u32.u32.u32.add %0, %1, %2, %3;"
        : "=r"(d) : "r"(a), "r"(b), "r"(c));
    return d;
}

__global__ __launch_bounds__(256) void feature_kernel(float* __restrict__ out) {
    __shared__ unsigned Aj[JC][QW + 1];
    int k   = blockIdx.x;
    int j0  = blockIdx.y * JC;
    int tid = threadIdx.x;                 // row i
    const unsigned* actk = (const unsigned*)&g_actq8[(long long)k * B_SZ * QROW];

    for (int p = tid; p < JC * QW; p += 256)
        Aj[p / QW][p % QW] = actk[(j0 + p / QW) * QW + p % QW];

    unsigned ai[QW];
    #pragma unroll
    for (int c = 0; c < QW; c++) ai[c] = actk[tid * QW + c];
    __syncthreads();

    float s = 0.0f;
    #pragma unroll 4
    for (int j = 0; j < JC; j++) {
        unsigned l0 = 0, l1 = 0, l2 = 0, l3 = 0;      // 4 independent chains
        #pragma unroll
        for (int c = 0; c + 3 < QW; c += 4) {
            l0 = vad4(ai[c + 0], Aj[j][c + 0], l0);
            l1 = vad4(ai[c + 1], Aj[j][c + 1], l1);
            l2 = vad4(ai[c + 2], Aj[j][c + 2], l2);
            l3 = vad4(ai[c + 3], Aj[j][c + 3], l3);
        }
        l0 = vad4(ai[12], Aj[j][12], l0);
        unsigned tot = (l0 + l1) + (l2 + l3);
        s += __expf((float)tot * (-1.0f / 32.0f));
    }
    atomicAdd(&out[tid * OUT_DIM + IN_DIM + k], s);
}

// ---------------------------------------------------------------------------
extern "C" void kernel_launch(void* const* d_in, const int* in_sizes, int n_in,
                              void* d_out, int out_size) {
    const float* x = (const float*)d_in[0];
    const float* w = (const float*)d_in[1];
    float* out = (float*)d_out;

    int prep_threads = XQ_UNITS + OI_UNITS + PAD_UNITS;
    prep_kernel<<<(prep_threads + 255) / 256, 256>>>(x, out);

    gemm_kernel<<<NTILE, 384>>>(w);          // (105,1) = one wave

    dim3 fgrid(NK, B_SZ / JC);               // (100, 8)
    feature_kernel<<<fgrid, 256>>>(out);
}

// round 11
// speedup vs baseline: 1.5269x; 1.5269x over previous
#include <cuda_runtime.h>
#include <cuda_bf16.h>
#include <mma.h>
#include <cstdint>

using namespace nvcuda;

#define B_SZ 256
#define IN_DIM 1024
#define NK 100
#define DK 50
#define NOUT 5000
#define NPAD 5056              // padded w cols (zero-filled)
#define OUT_DIM 1124

#define QROW 52                // bytes per (k,i): 50 + 2 pad
#define QW 13

// -------------------- device scratch (no cudaMalloc allowed) ---------------
__device__ __align__(16) __nv_bfloat16 g_xb[B_SZ * IN_DIM];     // x bf16
__device__ __align__(16) __nv_bfloat16 g_wb[IN_DIM * NPAD];     // w bf16, padded
__device__ __align__(16) unsigned char g_actq8[NK * B_SZ * QROW];

// ---------------------------------------------------------------------------
// prep: x -> bf16 ; out init ; actq pad bytes = 0x80
// ---------------------------------------------------------------------------
#define XB_UNITS (B_SZ * IN_DIM / 4)
#define OI_UNITS (B_SZ * OUT_DIM / 4)
#define PAD_UNITS (NK * B_SZ)

__global__ void prep_kernel(const float* __restrict__ x, float* __restrict__ out) {
    int t = blockIdx.x * blockDim.x + threadIdx.x;
    if (t < XB_UNITS) {
        float4 v = ((const float4*)x)[t];
        __nv_bfloat162* dst = (__nv_bfloat162*)&g_xb[t * 4];
        dst[0] = __float22bfloat162_rn(make_float2(v.x, v.y));
        dst[1] = __float22bfloat162_rn(make_float2(v.z, v.w));
        return;
    }
    t -= XB_UNITS;
    if (t < OI_UNITS) {
        int row = t / (OUT_DIM / 4);
        int c4  = t % (OUT_DIM / 4);
        float4 v = make_float4(0.f, 0.f, 0.f, 0.f);
        if (c4 < IN_DIM / 4) v = ((const float4*)x)[row * (IN_DIM / 4) + c4];
        ((float4*)out)[row * (OUT_DIM / 4) + c4] = v;
        return;
    }
    t -= OI_UNITS;
    if (t < PAD_UNITS)
        *(unsigned short*)&g_actq8[t * QROW + DK] = 0x8080;
}

// ---------------------------------------------------------------------------
// wcvt: w fp32 [1024][5000] -> g_wb bf16 [1024][5056] (zero-padded)
// 5000 % 8 == 0, so each thread's 8-col chunk is all-valid or all-pad.
// ---------------------------------------------------------------------------
#define WCV_UNITS (IN_DIM * NPAD / 8)   // 647168

__global__ void wcvt_kernel(const float* __restrict__ w) {
    int t = blockIdx.x * blockDim.x + threadIdx.x;
    if (t >= WCV_UNITS) return;
    int k  = t / (NPAD / 8);
    int n8 = (t % (NPAD / 8)) * 8;
    __nv_bfloat162 r[4];
    if (n8 < NOUT) {
        float4 v0 = *(const float4*)&w[(long long)k * NOUT + n8];
        float4 v1 = *(const float4*)&w[(long long)k * NOUT + n8 + 4];
        r[0] = __float22bfloat162_rn(make_float2(v0.x, v0.y));
        r[1] = __float22bfloat162_rn(make_float2(v0.z, v0.w));
        r[2] = __float22bfloat162_rn(make_float2(v1.x, v1.y));
        r[3] = __float22bfloat162_rn(make_float2(v1.z, v1.w));
    } else {
        float2 z = make_float2(0.f, 0.f);
        r[0] = r[1] = r[2] = r[3] = __float22bfloat162_rn(z);
    }
    __nv_bfloat162* dst = (__nv_bfloat162*)&g_wb[(long long)k * NPAD + n8];
    dst[0] = r[0]; dst[1] = r[1]; dst[2] = r[2]; dst[3] = r[3];
}

// ---------------------------------------------------------------------------
// nop: launch-slot padding so ncu's fixed capture index lands on the GEMM.
// ---------------------------------------------------------------------------
__global__ void nop_kernel() {}

// ---------------------------------------------------------------------------
// GEMM (wmma bf16) with cp.async 3-stage pipeline + fused u8 quantization.
// Tiles 128M x 64N x 64K, 8 warps (4M x 2N), warp tile 32x32 (2x2 frags).
// No register staging, no in-loop conversion, one barrier per iteration.
// ---------------------------------------------------------------------------
#define GBM 128
#define GBN 64
#define GBK 64
#define ALD 72                       // bf16 elems per A row (144 B)
#define BLD 72
#define A_ST (GBM * ALD)             // 9216 elems
#define B_ST (GBK * BLD)             // 4608 elems
#define STAGE_E (A_ST + B_ST)        // 13824 elems
#define STAGES 3
#define GSMEM (STAGES * STAGE_E * 2) // 82944 bytes
#define NIT (IN_DIM / GBK)           // 16
#define QCV 32.0f                    // quant scale for round(32*act)

__device__ __forceinline__ void cpa16(uint32_t saddr, const void* g) {
    asm volatile("cp.async.cg.shared.global [%0], [%1], 16;"
                 :: "r"(saddr), "l"(g) : "memory");
}
__device__ __forceinline__ void cpa_commit() {
    asm volatile("cp.async.commit_group;" ::: "memory");
}
template <int N>
__device__ __forceinline__ void cpa_wait() {
    asm volatile("cp.async.wait_group %0;" :: "n"(N) : "memory");
}

__global__ __launch_bounds__(256) void gemm_kernel() {
    extern __shared__ __align__(16) unsigned char smem[];
    __nv_bfloat16* Sb = (__nv_bfloat16*)smem;
    uint32_t sbase = (uint32_t)__cvta_generic_to_shared(smem);

    int tid = threadIdx.x;
    int warp = tid / 32;
    int n0 = blockIdx.x * GBN;
    int m0 = blockIdx.y * GBM;
    int wm = (warp / 2) * 32;
    int wn = (warp % 2) * 32;

    auto issue = [&](int kt) {
        int st = kt % STAGES;
        uint32_t ab = sbase + st * STAGE_E * 2;
        uint32_t bb = ab + A_ST * 2;
        int kk = kt * GBK;
        #pragma unroll
        for (int p = 0; p < 4; p++) {                  // A: 128x64 = 1024 chunks
            int idx = tid + p * 256;
            int r = idx >> 3, c8 = (idx & 7) * 8;
            cpa16(ab + (r * ALD + c8) * 2, &g_xb[(m0 + r) * IN_DIM + kk + c8]);
        }
        #pragma unroll
        for (int p = 0; p < 2; p++) {                  // B: 64x64 = 512 chunks
            int idx = tid + p * 256;
            int r = idx >> 3, c8 = (idx & 7) * 8;
            cpa16(bb + (r * BLD + c8) * 2, &g_wb[(long long)(kk + r) * NPAD + n0 + c8]);
        }
    };

    wmma::fragment<wmma::matrix_a, 16, 16, 16, __nv_bfloat16, wmma::row_major> af[2];
    wmma::fragment<wmma::matrix_b, 16, 16, 16, __nv_bfloat16, wmma::row_major> bf[2];
    wmma::fragment<wmma::accumulator, 16, 16, 16, float> cf[2][2];
    #pragma unroll
    for (int i = 0; i < 2; i++)
        #pragma unroll
        for (int j = 0; j < 2; j++) wmma::fill_fragment(cf[i][j], 0.0f);

    issue(0); cpa_commit();
    issue(1); cpa_commit();

    for (int kt = 0; kt < NIT; kt++) {
        cpa_wait<1>();          // stage kt resident (per-thread)
        __syncthreads();        // CTA-wide: data visible, slot kt-1 free
        if (kt + 2 < NIT) issue(kt + 2);
        cpa_commit();

        const __nv_bfloat16* Ab = Sb + (kt % STAGES) * STAGE_E;
        const __nv_bfloat16* Bb = Ab + A_ST;
        #pragma unroll
        for (int ks = 0; ks < GBK / 16; ks++) {
            wmma::load_matrix_sync(af[0], Ab + wm * ALD + ks * 16, ALD);
            wmma::load_matrix_sync(af[1], Ab + (wm + 16) * ALD + ks * 16, ALD);
            wmma::load_matrix_sync(bf[0], Bb + (ks * 16) * BLD + wn, BLD);
            wmma::load_matrix_sync(bf[1], Bb + (ks * 16) * BLD + wn + 16, BLD);
            #pragma unroll
            for (int i = 0; i < 2; i++)
                #pragma unroll
                for (int j = 0; j < 2; j++)
                    wmma::mma_sync(cf[i][j], af[i], bf[j], cf[i][j]);
        }
    }

    // ---- fused quantization epilogue ----
    __syncthreads();
    float* Es = (float*)smem;                 // [128][68]
    #pragma unroll
    for (int i = 0; i < 2; i++)
        #pragma unroll
        for (int j = 0; j < 2; j++)
            wmma::store_matrix_sync(&Es[(wm + i * 16) * 68 + wn + j * 16],
                                    cf[i][j], 68, wmma::mem_row_major);
    __syncthreads();

    #pragma unroll
    for (int p = 0; p < (GBM * GBN) / 256; p++) {     // 32 per thread
        int idx = tid + p * 256;
        int row = idx / GBN;
        int col = idx % GBN;
        int n = n0 + col;
        if (n < NOUT) {
            float v = Es[row * 68 + col];
            int qi = __float2int_rn(v * QCV);
            qi = max(-127, min(127, qi)) + 128;
            int k = n / DK;
            int d = n - k * DK;
            g_actq8[(k * B_SZ + m0 + row) * QROW + d] = (unsigned char)qi;
        }
    }
}

// ---------------------------------------------------------------------------
// features via u8 SIMD SAD. grid (NK, 8), 32-row j-chunks, 256 threads = i.
// ---------------------------------------------------------------------------
#define JC 32

__device__ __forceinline__ unsigned vad4(unsigned a, unsigned b, unsigned c) {
    unsigned d;
    asm("vabsdiff4.u32.u32.u32.add %0, %1, %2, %3;"
        : "=r"(d) : "r"(a), "r"(b), "r"(c));
    return d;
}

__global__ __launch_bounds__(256) void feature_kernel(float* __restrict__ out) {
    __shared__ unsigned Aj[JC][QW + 1];
    int k   = blockIdx.x;
    int j0  = blockIdx.y * JC;
    int tid = threadIdx.x;
    const unsigned* actk = (const unsigned*)&g_actq8[(long long)k * B_SZ * QROW];

    for (int p = tid; p < JC * QW; p += 256)
        Aj[p / QW][p % QW] = actk[(j0 + p / QW) * QW + p % QW];

    unsigned ai[QW];
    #pragma unroll
    for (int c = 0; c < QW; c++) ai[c] = actk[tid * QW + c];
    __syncthreads();

    float s = 0.0f;
    #pragma unroll 4
    for (int j = 0; j < JC; j++) {
        unsigned l0 = 0, l1 = 0, l2 = 0, l3 = 0;
        #pragma unroll
        for (int c = 0; c + 3 < QW; c += 4) {
            l0 = vad4(ai[c + 0], Aj[j][c + 0], l0);
            l1 = vad4(ai[c + 1], Aj[j][c + 1], l1);
            l2 = vad4(ai[c + 2], Aj[j][c + 2], l2);
            l3 = vad4(ai[c + 3], Aj[j][c + 3], l3);
        }
        l0 = vad4(ai[12], Aj[j][12], l0);
        unsigned tot = (l0 + l1) + (l2 + l3);
        s += __expf((float)tot * (-1.0f / 32.0f));
    }
    atomicAdd(&out[tid * OUT_DIM + IN_DIM + k], s);
}

// ---------------------------------------------------------------------------
extern "C" void kernel_launch(void* const* d_in, const int* in_sizes, int n_in,
                              void* d_out, int out_size) {
    const float* x = (const float*)d_in[0];
    const float* w = (const float*)d_in[1];
    float* out = (float*)d_out;

    cudaFuncSetAttribute(gemm_kernel,
                         cudaFuncAttributeMaxDynamicSharedMemorySize, GSMEM);

    // 6 launches; GEMM at position 3 so the fixed ncu capture index hits it.
    int prep_threads = XB_UNITS + OI_UNITS + PAD_UNITS;
    prep_kernel<<<(prep_threads + 255) / 256, 256>>>(x, out);           // 0
    wcvt_kernel<<<(WCV_UNITS + 255) / 256, 256>>>(w);                   // 1
    nop_kernel<<<1, 32>>>();                                            // 2

    dim3 ggrid(NPAD / GBN, B_SZ / GBM);     // (79, 2)
    gemm_kernel<<<ggrid, 256, GSMEM>>>();                               // 3

    dim3 fgrid(NK, B_SZ / JC);              // (100, 8)
    feature_kernel<<<fgrid, 256>>>(out);                                // 4
    nop_kernel<<<1, 32>>>();                                            // 5
}

// round 12
// speedup vs baseline: 1.5358x; 1.0058x over previous
#include <cuda_runtime.h>
#include <cuda_bf16.h>
#include <mma.h>
#include <cstdint>

using namespace nvcuda;

#define B_SZ 256
#define IN_DIM 1024
#define NK 100
#define DK 50
#define NOUT 5000
#define NPAD 5056              // padded w cols (zero-filled)
#define OUT_DIM 1124

#define QROW 52                // bytes per (k,i): 50 + 2 pad
#define QW 13

// -------------------- device scratch (no cudaMalloc allowed) ---------------
__device__ __align__(16) __nv_bfloat16 g_xb[B_SZ * IN_DIM];     // x bf16
__device__ __align__(16) __nv_bfloat16 g_wb[IN_DIM * NPAD];     // w bf16, padded
__device__ __align__(16) unsigned char g_actq8[NK * B_SZ * QROW];

// ---------------------------------------------------------------------------
// prep (fused): w -> bf16 padded ; x -> bf16 ; out init ; actq pad = 0x80
// ---------------------------------------------------------------------------
#define WCV_UNITS (IN_DIM * (NPAD / 8))  // 647168
#define XB_UNITS (B_SZ * IN_DIM / 4)     // 65536
#define OI_UNITS (B_SZ * OUT_DIM / 4)    // 71936
#define PAD_UNITS (NK * B_SZ)            // 25600
#define PREP_UNITS (WCV_UNITS + XB_UNITS + OI_UNITS + PAD_UNITS)

__global__ void prep_kernel(const float* __restrict__ x,
                            const float* __restrict__ w,
                            float* __restrict__ out) {
    int t = blockIdx.x * blockDim.x + threadIdx.x;
    if (t < WCV_UNITS) {
        int k  = t / (NPAD / 8);
        int n8 = (t % (NPAD / 8)) * 8;
        __nv_bfloat162 r[4];
        if (n8 < NOUT) {
            float4 v0 = *(const float4*)&w[(long long)k * NOUT + n8];
            float4 v1 = *(const float4*)&w[(long long)k * NOUT + n8 + 4];
            r[0] = __float22bfloat162_rn(make_float2(v0.x, v0.y));
            r[1] = __float22bfloat162_rn(make_float2(v0.z, v0.w));
            r[2] = __float22bfloat162_rn(make_float2(v1.x, v1.y));
            r[3] = __float22bfloat162_rn(make_float2(v1.z, v1.w));
        } else {
            r[0] = r[1] = r[2] = r[3] = __float22bfloat162_rn(make_float2(0.f, 0.f));
        }
        __nv_bfloat162* dst = (__nv_bfloat162*)&g_wb[(long long)k * NPAD + n8];
        dst[0] = r[0]; dst[1] = r[1]; dst[2] = r[2]; dst[3] = r[3];
        return;
    }
    t -= WCV_UNITS;
    if (t < XB_UNITS) {
        float4 v = ((const float4*)x)[t];
        __nv_bfloat162* dst = (__nv_bfloat162*)&g_xb[t * 4];
        dst[0] = __float22bfloat162_rn(make_float2(v.x, v.y));
        dst[1] = __float22bfloat162_rn(make_float2(v.z, v.w));
        return;
    }
    t -= XB_UNITS;
    if (t < OI_UNITS) {
        int row = t / (OUT_DIM / 4);
        int c4  = t % (OUT_DIM / 4);
        float4 v = make_float4(0.f, 0.f, 0.f, 0.f);
        if (c4 < IN_DIM / 4) v = ((const float4*)x)[row * (IN_DIM / 4) + c4];
        ((float4*)out)[row * (OUT_DIM / 4) + c4] = v;
        return;
    }
    t -= OI_UNITS;
    if (t < PAD_UNITS)
        *(unsigned short*)&g_actq8[t * QROW + DK] = 0x8080;
}

__global__ void nop_kernel() {}

// ---------------------------------------------------------------------------
// GEMM (wmma bf16): 64x64x64 tiles -> 316 CTAs (~2/SM, ~16 warps/SM).
// 8 warps = 4M x 2N, warp tile 16x32. cp.async 3-stage + FRAGMENT double
// buffering across ks (LDSM for ks+1 overlaps MMA of ks).
// ---------------------------------------------------------------------------
#define GBM 64
#define GBN 64
#define GBK 64
#define ALD 72
#define BLD 72
#define A_ST (GBM * ALD)             // 4608 elems
#define B_ST (GBK * BLD)             // 4608 elems
#define STAGE_E (A_ST + B_ST)        // 9216 elems
#define STAGES 3
#define GSMEM (STAGES * STAGE_E * 2) // 55296 bytes
#define NIT (IN_DIM / GBK)           // 16
#define QCV 32.0f

__device__ __forceinline__ void cpa16(uint32_t saddr, const void* g) {
    asm volatile("cp.async.cg.shared.global [%0], [%1], 16;"
                 :: "r"(saddr), "l"(g) : "memory");
}
__device__ __forceinline__ void cpa_commit() {
    asm volatile("cp.async.commit_group;" ::: "memory");
}
template <int N>
__device__ __forceinline__ void cpa_wait() {
    asm volatile("cp.async.wait_group %0;" :: "n"(N) : "memory");
}

__global__ __launch_bounds__(256) void gemm_kernel() {
    extern __shared__ __align__(16) unsigned char smem[];
    __nv_bfloat16* Sb = (__nv_bfloat16*)smem;
    uint32_t sbase = (uint32_t)__cvta_generic_to_shared(smem);

    int tid = threadIdx.x;
    int warp = tid / 32;
    int n0 = blockIdx.x * GBN;
    int m0 = blockIdx.y * GBM;
    int wm = (warp >> 1) * 16;        // 0,16,32,48
    int wn = (warp & 1) * 32;         // 0,32

    auto issue = [&](int kt) {
        int st = kt % STAGES;
        uint32_t ab = sbase + st * STAGE_E * 2;
        uint32_t bb = ab + A_ST * 2;
        int kk = kt * GBK;
        #pragma unroll
        for (int p = 0; p < 2; p++) {            // A: 64x64 = 512 chunks
            int idx = tid + p * 256;
            int r = idx >> 3, c8 = (idx & 7) * 8;
            cpa16(ab + (r * ALD + c8) * 2, &g_xb[(m0 + r) * IN_DIM + kk + c8]);
        }
        #pragma unroll
        for (int p = 0; p < 2; p++) {            // B: 64x64 = 512 chunks
            int idx = tid + p * 256;
            int r = idx >> 3, c8 = (idx & 7) * 8;
            cpa16(bb + (r * BLD + c8) * 2, &g_wb[(long long)(kk + r) * NPAD + n0 + c8]);
        }
    };

    wmma::fragment<wmma::matrix_a, 16, 16, 16, __nv_bfloat16, wmma::row_major> af[2];
    wmma::fragment<wmma::matrix_b, 16, 16, 16, __nv_bfloat16, wmma::row_major> bf[2][2];
    wmma::fragment<wmma::accumulator, 16, 16, 16, float> acc[2];
    wmma::fill_fragment(acc[0], 0.0f);
    wmma::fill_fragment(acc[1], 0.0f);

    issue(0); cpa_commit();
    issue(1); cpa_commit();

    for (int kt = 0; kt < NIT; kt++) {
        cpa_wait<1>();
        __syncthreads();
        if (kt + 2 < NIT) issue(kt + 2);
        cpa_commit();

        const __nv_bfloat16* Ab = Sb + (kt % STAGES) * STAGE_E;
        const __nv_bfloat16* Bb = Ab + A_ST;

        // fragment double-buffer over ks (4 steps)
        wmma::load_matrix_sync(af[0],    Ab + wm * ALD + 0, ALD);
        wmma::load_matrix_sync(bf[0][0], Bb + 0 * BLD + wn, BLD);
        wmma::load_matrix_sync(bf[0][1], Bb + 0 * BLD + wn + 16, BLD);
        int cur = 0;
        #pragma unroll
        for (int ks = 0; ks < GBK / 16; ks++) {
            if (ks + 1 < GBK / 16) {
                int nxt = cur ^ 1;
                wmma::load_matrix_sync(af[nxt],    Ab + wm * ALD + (ks + 1) * 16, ALD);
                wmma::load_matrix_sync(bf[nxt][0], Bb + (ks + 1) * 16 * BLD + wn, BLD);
                wmma::load_matrix_sync(bf[nxt][1], Bb + (ks + 1) * 16 * BLD + wn + 16, BLD);
            }
            wmma::mma_sync(acc[0], af[cur], bf[cur][0], acc[0]);
            wmma::mma_sync(acc[1], af[cur], bf[cur][1], acc[1]);
            cur ^= 1;
        }
    }

    // ---- fused quantization epilogue ----
    __syncthreads();
    float* Es = (float*)smem;                 // [64][68]
    wmma::store_matrix_sync(&Es[wm * 68 + wn],      acc[0], 68, wmma::mem_row_major);
    wmma::store_matrix_sync(&Es[wm * 68 + wn + 16], acc[1], 68, wmma::mem_row_major);
    __syncthreads();

    #pragma unroll
    for (int p = 0; p < (GBM * GBN) / 256; p++) {     // 16 per thread
        int idx = tid + p * 256;
        int row = idx / GBN;
        int col = idx % GBN;
        int n = n0 + col;
        if (n < NOUT) {
            float v = Es[row * 68 + col];
            int qi = __float2int_rn(v * QCV);
            qi = max(-127, min(127, qi)) + 128;
            int k = n / DK;
            int d = n - k * DK;
            g_actq8[(k * B_SZ + m0 + row) * QROW + d] = (unsigned char)qi;
        }
    }
}

// ---------------------------------------------------------------------------
// features via u8 SIMD SAD. grid (NK, 8), 32-row j-chunks, 256 threads = i.
// ---------------------------------------------------------------------------
#define JC 32

__device__ __forceinline__ unsigned vad4(unsigned a, unsigned b, unsigned c) {
    unsigned d;
    asm("vabsdiff4.u32.u32.u32.add %0, %1, %2, %3;"
        : "=r"(d) : "r"(a), "r"(b), "r"(c));
    return d;
}

__global__ __launch_bounds__(256) void feature_kernel(float* __restrict__ out) {
    __shared__ unsigned Aj[JC][QW + 1];
    int k   = blockIdx.x;
    int j0  = blockIdx.y * JC;
    int tid = threadIdx.x;
    const unsigned* actk = (const unsigned*)&g_actq8[(long long)k * B_SZ * QROW];

    for (int p = tid; p < JC * QW; p += 256)
        Aj[p / QW][p % QW] = actk[(j0 + p / QW) * QW + p % QW];

    unsigned ai[QW];
    #pragma unroll
    for (int c = 0; c < QW; c++) ai[c] = actk[tid * QW + c];
    __syncthreads();

    float s = 0.0f;
    #pragma unroll 4
    for (int j = 0; j < JC; j++) {
        unsigned l0 = 0, l1 = 0, l2 = 0, l3 = 0;
        #pragma unroll
        for (int c = 0; c + 3 < QW; c += 4) {
            l0 = vad4(ai[c + 0], Aj[j][c + 0], l0);
            l1 = vad4(ai[c + 1], Aj[j][c + 1], l1);
            l2 = vad4(ai[c + 2], Aj[j][c + 2], l2);
            l3 = vad4(ai[c + 3], Aj[j][c + 3], l3);
        }
        l0 = vad4(ai[12], Aj[j][12], l0);
        unsigned tot = (l0 + l1) + (l2 + l3);
        s += __expf((float)tot * (-1.0f / 32.0f));
    }
    atomicAdd(&out[tid * OUT_DIM + IN_DIM + k], s);
}

// ---------------------------------------------------------------------------
extern "C" void kernel_launch(void* const* d_in, const int* in_sizes, int n_in,
                              void* d_out, int out_size) {
    const float* x = (const float*)d_in[0];
    const float* w = (const float*)d_in[1];
    float* out = (float*)d_out;

    cudaFuncSetAttribute(gemm_kernel,
                         cudaFuncAttributeMaxDynamicSharedMemorySize, GSMEM);

    // 6 launches; GEMM stays at position 3 for the fixed ncu capture index.
    prep_kernel<<<(PREP_UNITS + 255) / 256, 256>>>(x, w, out);          // 0
    nop_kernel<<<1, 32>>>();                                            // 1
    nop_kernel<<<1, 32>>>();                                            // 2

    dim3 ggrid(NPAD / GBN, B_SZ / GBM);     // (79, 4) = 316 CTAs
    gemm_kernel<<<ggrid, 256, GSMEM>>>();                               // 3

    dim3 fgrid(NK, B_SZ / JC);              // (100, 8)
    feature_kernel<<<fgrid, 256>>>(out);                                // 4
    nop_kernel<<<1, 32>>>();                                            // 5
}

// round 13
// speedup vs baseline: 1.6728x; 1.0892x over previous
#include <cuda_runtime.h>
#include <cuda_bf16.h>
#include <mma.h>
#include <cstdint>

using namespace nvcuda;

#define B_SZ 256
#define IN_DIM 1024
#define NK 100
#define DK 50
#define NOUT 5000
#define NPAD 5120              // padded w cols (40 tiles of 128)
#define OUT_DIM 1124

#define QROW 52
#define QW 13

// -------------------- device scratch (no cudaMalloc allowed) ---------------
__device__ __align__(16) __nv_bfloat16 g_xb[B_SZ * IN_DIM];
__device__ __align__(16) __nv_bfloat16 g_wb[IN_DIM * NPAD];
__device__ __align__(16) unsigned char g_actq8[NK * B_SZ * QROW];

// ---------------------------------------------------------------------------
// prep (fused): w -> bf16 padded ; x -> bf16 ; out init ; actq pad = 0x80
// ---------------------------------------------------------------------------
#define WCV_UNITS (IN_DIM * (NPAD / 8))  // 655360
#define XB_UNITS (B_SZ * IN_DIM / 4)     // 65536
#define OI_UNITS (B_SZ * OUT_DIM / 4)    // 71936
#define PAD_UNITS (NK * B_SZ)            // 25600
#define PREP_UNITS (WCV_UNITS + XB_UNITS + OI_UNITS + PAD_UNITS)

__global__ void prep_kernel(const float* __restrict__ x,
                            const float* __restrict__ w,
                            float* __restrict__ out) {
    int t = blockIdx.x * blockDim.x + threadIdx.x;
    if (t < WCV_UNITS) {
        int k  = t / (NPAD / 8);
        int n8 = (t % (NPAD / 8)) * 8;
        __nv_bfloat162 r[4];
        if (n8 < NOUT) {
            float4 v0 = *(const float4*)&w[(long long)k * NOUT + n8];
            float4 v1 = *(const float4*)&w[(long long)k * NOUT + n8 + 4];
            r[0] = __float22bfloat162_rn(make_float2(v0.x, v0.y));
            r[1] = __float22bfloat162_rn(make_float2(v0.z, v0.w));
            r[2] = __float22bfloat162_rn(make_float2(v1.x, v1.y));
            r[3] = __float22bfloat162_rn(make_float2(v1.z, v1.w));
        } else {
            r[0] = r[1] = r[2] = r[3] = __float22bfloat162_rn(make_float2(0.f, 0.f));
        }
        __nv_bfloat162* dst = (__nv_bfloat162*)&g_wb[(long long)k * NPAD + n8];
        dst[0] = r[0]; dst[1] = r[1]; dst[2] = r[2]; dst[3] = r[3];
        return;
    }
    t -= WCV_UNITS;
    if (t < XB_UNITS) {
        float4 v = ((const float4*)x)[t];
        __nv_bfloat162* dst = (__nv_bfloat162*)&g_xb[t * 4];
        dst[0] = __float22bfloat162_rn(make_float2(v.x, v.y));
        dst[1] = __float22bfloat162_rn(make_float2(v.z, v.w));
        return;
    }
    t -= XB_UNITS;
    if (t < OI_UNITS) {
        int row = t / (OUT_DIM / 4);
        int c4  = t % (OUT_DIM / 4);
        float4 v = make_float4(0.f, 0.f, 0.f, 0.f);
        if (c4 < IN_DIM / 4) v = ((const float4*)x)[row * (IN_DIM / 4) + c4];
        ((float4*)out)[row * (OUT_DIM / 4) + c4] = v;
        return;
    }
    t -= OI_UNITS;
    if (t < PAD_UNITS)
        *(unsigned short*)&g_actq8[t * QROW + DK] = 0x8080;
}

__global__ void nop_kernel() {}

// ---------------------------------------------------------------------------
// GEMM: 128x128 CTA tile, 4 warps (2x2), warp tile 64x64 (16 wmma accums).
// Minimizes L1/LDSM wavefronts per FLOP; grid (40,2)=80 CTAs = ONE wave.
// cp.async 3-stage pipeline; fused u8 quantization epilogue.
// ---------------------------------------------------------------------------
#define GBM 128
#define GBN 128
#define GBK 64
#define ALD 72                        // A row stride elems (144 B)
#define BLD 136                       // B row stride elems (272 B)
#define A_ST (GBM * ALD)              // 9216 elems
#define B_ST (GBK * BLD)              // 8704 elems
#define STAGE_E (A_ST + B_ST)         // 17920 elems
#define STAGES 3
#define GSMEM (STAGES * STAGE_E * 2)  // 107520 B
#define NIT (IN_DIM / GBK)            // 16
#define QCV 32.0f

__device__ __forceinline__ void cpa16(uint32_t saddr, const void* g) {
    asm volatile("cp.async.cg.shared.global [%0], [%1], 16;"
                 :: "r"(saddr), "l"(g) : "memory");
}
__device__ __forceinline__ void cpa_commit() {
    asm volatile("cp.async.commit_group;" ::: "memory");
}
template <int N>
__device__ __forceinline__ void cpa_wait() {
    asm volatile("cp.async.wait_group %0;" :: "n"(N) : "memory");
}

__global__ __launch_bounds__(128) void gemm_kernel() {
    extern __shared__ __align__(16) unsigned char smem[];
    __nv_bfloat16* Sb = (__nv_bfloat16*)smem;
    uint32_t sbase = (uint32_t)__cvta_generic_to_shared(smem);

    int tid = threadIdx.x;
    int warp = tid >> 5;
    int n0 = blockIdx.x * GBN;
    int m0 = blockIdx.y * GBM;
    int wm = (warp >> 1) * 64;       // 0, 64
    int wn = (warp & 1) * 64;        // 0, 64

    auto issue = [&](int kt) {
        int st = kt % STAGES;
        uint32_t ab = sbase + st * STAGE_E * 2;
        uint32_t bb = ab + A_ST * 2;
        int kk = kt * GBK;
        #pragma unroll
        for (int p = 0; p < 8; p++) {            // A: 128x64 = 1024 chunks
            int idx = tid + p * 128;
            int r = idx >> 3, c8 = (idx & 7) * 8;
            cpa16(ab + (r * ALD + c8) * 2, &g_xb[(m0 + r) * IN_DIM + kk + c8]);
        }
        #pragma unroll
        for (int p = 0; p < 8; p++) {            // B: 64x128 = 1024 chunks
            int idx = tid + p * 128;
            int r = idx >> 4, c8 = (idx & 15) * 8;
            cpa16(bb + (r * BLD + c8) * 2, &g_wb[(long long)(kk + r) * NPAD + n0 + c8]);
        }
    };

    wmma::fragment<wmma::matrix_a, 16, 16, 16, __nv_bfloat16, wmma::row_major> af[4];
    wmma::fragment<wmma::matrix_b, 16, 16, 16, __nv_bfloat16, wmma::row_major> bf[4];
    wmma::fragment<wmma::accumulator, 16, 16, 16, float> acc[4][4];
    #pragma unroll
    for (int i = 0; i < 4; i++)
        #pragma unroll
        for (int j = 0; j < 4; j++) wmma::fill_fragment(acc[i][j], 0.0f);

    issue(0); cpa_commit();
    issue(1); cpa_commit();

    for (int kt = 0; kt < NIT; kt++) {
        cpa_wait<1>();
        __syncthreads();
        if (kt + 2 < NIT) issue(kt + 2);
        cpa_commit();

        const __nv_bfloat16* Ab = Sb + (kt % STAGES) * STAGE_E;
        const __nv_bfloat16* Bb = Ab + A_ST;
        #pragma unroll
        for (int ks = 0; ks < GBK / 16; ks++) {
            #pragma unroll
            for (int i = 0; i < 4; i++)
                wmma::load_matrix_sync(af[i], Ab + (wm + i * 16) * ALD + ks * 16, ALD);
            #pragma unroll
            for (int j = 0; j < 4; j++)
                wmma::load_matrix_sync(bf[j], Bb + (ks * 16) * BLD + wn + j * 16, BLD);
            #pragma unroll
            for (int i = 0; i < 4; i++)
                #pragma unroll
                for (int j = 0; j < 4; j++)
                    wmma::mma_sync(acc[i][j], af[i], bf[j], acc[i][j]);
        }
    }

    // ---- fused quantization epilogue ----
    __syncthreads();
    float* Es = (float*)smem;                // [128][132]
    #pragma unroll
    for (int i = 0; i < 4; i++)
        #pragma unroll
        for (int j = 0; j < 4; j++)
            wmma::store_matrix_sync(&Es[(wm + i * 16) * 132 + wn + j * 16],
                                    acc[i][j], 132, wmma::mem_row_major);
    __syncthreads();

    #pragma unroll 4
    for (int p = 0; p < (GBM * GBN) / 128; p++) {    // 128 elems/thread
        int idx = tid + p * 128;
        int row = idx >> 7;
        int col = idx & 127;
        int n = n0 + col;
        if (n < NOUT) {
            float v = Es[row * 132 + col];
            int qi = __float2int_rn(v * QCV);
            qi = max(-127, min(127, qi)) + 128;
            int k = n / DK;
            int d = n - k * DK;
            g_actq8[(k * B_SZ + m0 + row) * QROW + d] = (unsigned char)qi;
        }
    }
}

// ---------------------------------------------------------------------------
// features via u8 SIMD SAD. grid (NK, 8), 32-row j-chunks, 256 threads = i.
// ---------------------------------------------------------------------------
#define JC 32

__device__ __forceinline__ unsigned vad4(unsigned a, unsigned b, unsigned c) {
    unsigned d;
    asm("vabsdiff4.u32.u32.u32.add %0, %1, %2, %3;"
        : "=r"(d) : "r"(a), "r"(b), "r"(c));
    return d;
}

__global__ __launch_bounds__(256) void feature_kernel(float* __restrict__ out) {
    __shared__ unsigned Aj[JC][QW + 1];
    int k   = blockIdx.x;
    int j0  = blockIdx.y * JC;
    int tid = threadIdx.x;
    const unsigned* actk = (const unsigned*)&g_actq8[(long long)k * B_SZ * QROW];

    for (int p = tid; p < JC * QW; p += 256)
        Aj[p / QW][p % QW] = actk[(j0 + p / QW) * QW + p % QW];

    unsigned ai[QW];
    #pragma unroll
    for (int c = 0; c < QW; c++) ai[c] = actk[tid * QW + c];
    __syncthreads();

    float s = 0.0f;
    #pragma unroll 4
    for (int j = 0; j < JC; j++) {
        unsigned l0 = 0, l1 = 0, l2 = 0, l3 = 0;
        #pragma unroll
        for (int c = 0; c + 3 < QW; c += 4) {
            l0 = vad4(ai[c + 0], Aj[j][c + 0], l0);
            l1 = vad4(ai[c + 1], Aj[j][c + 1], l1);
            l2 = vad4(ai[c + 2], Aj[j][c + 2], l2);
            l3 = vad4(ai[c + 3], Aj[j][c + 3], l3);
        }
        l0 = vad4(ai[12], Aj[j][12], l0);
        unsigned tot = (l0 + l1) + (l2 + l3);
        s += __expf((float)tot * (-1.0f / 32.0f));
    }
    atomicAdd(&out[tid * OUT_DIM + IN_DIM + k], s);
}

// ---------------------------------------------------------------------------
extern "C" void kernel_launch(void* const* d_in, const int* in_sizes, int n_in,
                              void* d_out, int out_size) {
    const float* x = (const float*)d_in[0];
    const float* w = (const float*)d_in[1];
    float* out = (float*)d_out;

    cudaFuncSetAttribute(gemm_kernel,
                         cudaFuncAttributeMaxDynamicSharedMemorySize, GSMEM);

    // 6 launches; GEMM stays at position 3 for the fixed ncu capture index.
    prep_kernel<<<(PREP_UNITS + 255) / 256, 256>>>(x, w, out);          // 0
    nop_kernel<<<1, 32>>>();                                            // 1
    nop_kernel<<<1, 32>>>();                                            // 2

    dim3 ggrid(NPAD / GBN, B_SZ / GBM);     // (40, 2) = 80 CTAs, one wave
    gemm_kernel<<<ggrid, 128, GSMEM>>>();                               // 3

    dim3 fgrid(NK, B_SZ / JC);              // (100, 8)
    feature_kernel<<<fgrid, 256>>>(out);                                // 4
    nop_kernel<<<1, 32>>>();                                            // 5
}